// round 4
// baseline (speedup 1.0000x reference)
#include <cuda_runtime.h>
#include <math.h>

#define NN 50000
#define DD 64
#define EE 1250000
#define BB 4096
#define ROW4 16              // float4 per embedding row

typedef unsigned long long u64;

// ---------------- scratch (device globals; no allocation) ----------------
__device__ float g_embA[NN * DD];
__device__ float g_embB[NN * DD];
__device__ float g_agg [NN * DD];
__device__ float g_ue[BB * 256];
__device__ float g_pe[BB * 256];
__device__ float g_ne[BB * 256];
// CSR build scratch
__device__ int   g_cnt[NN];
__device__ int   g_rowstart[NN + 1];
__device__ int   g_cursor[NN];
__device__ int   g_pcol[EE];
__device__ float g_pval[EE];

// ---------------- packed fp32x2 helpers (Blackwell) ----------------
__device__ __forceinline__ u64 fma2(u64 a, u64 b, u64 c) {
    u64 d;
    asm("fma.rn.f32x2 %0, %1, %2, %3;" : "=l"(d) : "l"(a), "l"(b), "l"(c));
    return d;
}
__device__ __forceinline__ u64 add2(u64 a, u64 b) {
    u64 d;
    asm("add.rn.f32x2 %0, %1, %2;" : "=l"(d) : "l"(a), "l"(b));
    return d;
}
__device__ __forceinline__ float hsum2(u64 v) {
    return __uint_as_float((unsigned)(v & 0xffffffffULL)) +
           __uint_as_float((unsigned)(v >> 32));
}

// ---------------- CSR build ----------------

__global__ void zero_cnt_kernel() {
    int i = blockIdx.x * blockDim.x + threadIdx.x;
    if (i < NN) g_cnt[i] = 0;
}

__global__ void hist_kernel(const int* __restrict__ rows) {
    int e = blockIdx.x * blockDim.x + threadIdx.x;
    if (e < EE) atomicAdd(&g_cnt[rows[e]], 1);
}

// Single-block exclusive scan of g_cnt -> g_rowstart / g_cursor.
#define SCAN_T 1024
#define SCAN_CH 49           // 49*1024 = 50176 >= NN
__global__ void scan_kernel() {
    __shared__ int part[SCAN_T];
    const int t = threadIdx.x;
    const int base = t * SCAN_CH;
    int s = 0;
#pragma unroll
    for (int i = 0; i < SCAN_CH; i++) {
        int idx = base + i;
        if (idx < NN) s += g_cnt[idx];
    }
    part[t] = s;
    __syncthreads();
    // Hillis-Steele inclusive scan
    for (int d = 1; d < SCAN_T; d <<= 1) {
        int v = 0;
        if (t >= d) v = part[t - d];
        __syncthreads();
        if (t >= d) part[t] += v;
        __syncthreads();
    }
    int run = part[t] - s;   // exclusive prefix for this chunk
    for (int i = 0; i < SCAN_CH; i++) {
        int idx = base + i;
        if (idx < NN) {
            g_rowstart[idx] = run;
            g_cursor[idx]   = run;
            run += g_cnt[idx];
        }
    }
    if (t == SCAN_T - 1) g_rowstart[NN] = part[SCAN_T - 1];
}

__global__ void scatter_kernel(const int*  __restrict__ rows,
                               const int*  __restrict__ cols,
                               const float* __restrict__ vals) {
    int e = blockIdx.x * blockDim.x + threadIdx.x;
    if (e >= EE) return;
    int r = rows[e];
    int p = atomicAdd(&g_cursor[r], 1);
    g_pcol[p] = cols[e];
    g_pval[p] = vals[e];
}

// ---------------- SpMM (CSR, atomic-free) ----------------
// One warp per row; lane l owns float2 chunk l of the 64-wide embedding.
// Writes g_agg fully (zeros for empty rows) -> no zero pass needed.
__global__ void __launch_bounds__(256) spmm_csr_kernel(const float* __restrict__ emb) {
    const int w = blockIdx.x * 8 + (threadIdx.x >> 5);
    if (w >= NN) return;
    const int lane = threadIdx.x & 31;
    const int s  = g_rowstart[w];
    const int e2 = g_rowstart[w + 1];
    const float2* __restrict__ xv = reinterpret_cast<const float2*>(emb);

    float2 acc0 = make_float2(0.f, 0.f);
    float2 acc1 = make_float2(0.f, 0.f);
    int p = s;
    for (; p + 1 < e2; p += 2) {
        int   c0 = __ldg(&g_pcol[p]);
        float v0 = __ldg(&g_pval[p]);
        int   c1 = __ldg(&g_pcol[p + 1]);
        float v1 = __ldg(&g_pval[p + 1]);
        float2 x0 = xv[(size_t)c0 * 32 + lane];
        float2 x1 = xv[(size_t)c1 * 32 + lane];
        acc0.x = fmaf(v0, x0.x, acc0.x); acc0.y = fmaf(v0, x0.y, acc0.y);
        acc1.x = fmaf(v1, x1.x, acc1.x); acc1.y = fmaf(v1, x1.y, acc1.y);
    }
    if (p < e2) {
        int   c = __ldg(&g_pcol[p]);
        float v = __ldg(&g_pval[p]);
        float2 x = xv[(size_t)c * 32 + lane];
        acc0.x = fmaf(v, x.x, acc0.x); acc0.y = fmaf(v, x.y, acc0.y);
    }
    acc0.x += acc1.x; acc0.y += acc1.y;
    reinterpret_cast<float2*>(g_agg)[(size_t)w * 32 + lane] = acc0;
}

// ---------------- fused dense layer ----------------
//   sx = (agg+emb) @ W1^T + b1
//   ox = agg * (emb @ W2^T + b2)
//   out = leaky_relu(sx + ox, 0.01)
#define AGG_STRIDE 68
#define SM_W1   0
#define SM_W2   4096
#define SM_B1   8192
#define SM_B2   8256
#define SM_AGG  8320
#define SM_FLOATS (8320 + 128 * AGG_STRIDE)   // 17024 floats = 68096 B

__global__ void __launch_bounds__(128, 3) dense_kernel(
        const float* __restrict__ src,
        const float* __restrict__ w1,
        const float* __restrict__ b1,
        const float* __restrict__ w2,
        const float* __restrict__ b2,
        float* __restrict__ dst) {
    extern __shared__ float sm[];
    float* sW1  = sm + SM_W1;
    float* sW2  = sm + SM_W2;
    float* sB1  = sm + SM_B1;
    float* sB2  = sm + SM_B2;
    float* sAgg = sm + SM_AGG;

    const int tid = threadIdx.x;
    for (int i = tid; i < DD * DD / 4; i += 128) {
        reinterpret_cast<float4*>(sW1)[i] = reinterpret_cast<const float4*>(w1)[i];
        reinterpret_cast<float4*>(sW2)[i] = reinterpret_cast<const float4*>(w2)[i];
    }
    if (tid < DD) { sB1[tid] = b1[tid]; sB2[tid] = b2[tid]; }

    const int base = blockIdx.x * 128;
    const int nrows = min(128, NN - base);

    const float4* aggv = reinterpret_cast<const float4*>(g_agg);
    for (int idx = tid; idx < nrows * ROW4; idx += 128) {
        int node = idx >> 4, c = idx & 15;
        reinterpret_cast<float4*>(&sAgg[node * AGG_STRIDE])[c] =
            aggv[(size_t)(base + node) * ROW4 + c];
    }
    __syncthreads();

    if (tid < nrows) {
        const int n = base + tid;
        u64 x2[32], ax2[32];
        const ulonglong2* xr =
            reinterpret_cast<const ulonglong2*>(src + (size_t)n * DD);
        const ulonglong2* ar =
            reinterpret_cast<const ulonglong2*>(&sAgg[tid * AGG_STRIDE]);
#pragma unroll
        for (int c = 0; c < ROW4; c++) {
            ulonglong2 xv = xr[c];
            ulonglong2 av = ar[c];
            x2 [2*c]   = xv.x;             x2 [2*c+1] = xv.y;
            ax2[2*c]   = add2(xv.x, av.x); ax2[2*c+1] = add2(xv.y, av.y);
        }

        for (int j = 0; j < DD; j++) {
            u64 a0 = 0, a1 = 0, c0 = 0, c1 = 0;
            const ulonglong2* w1r = reinterpret_cast<const ulonglong2*>(&sW1[j * DD]);
            const ulonglong2* w2r = reinterpret_cast<const ulonglong2*>(&sW2[j * DD]);
#pragma unroll
            for (int k = 0; k < ROW4; k++) {
                ulonglong2 w1v = w1r[k];
                ulonglong2 w2v = w2r[k];
                a0 = fma2(ax2[2*k],   w1v.x, a0);
                a1 = fma2(ax2[2*k+1], w1v.y, a1);
                c0 = fma2(x2 [2*k],   w2v.x, c0);
                c1 = fma2(x2 [2*k+1], w2v.y, c1);
            }
            float s1 = sB1[j] + hsum2(a0) + hsum2(a1);
            float s2 = sB2[j] + hsum2(c0) + hsum2(c1);
            float aj = sAgg[tid * AGG_STRIDE + j];
            float v = s1 + aj * s2;
            sAgg[tid * AGG_STRIDE + j] = v > 0.f ? v : 0.01f * v;
        }
    }
    __syncthreads();

    float4* dstv = reinterpret_cast<float4*>(dst);
    for (int idx = tid; idx < nrows * ROW4; idx += 128) {
        int node = idx >> 4, c = idx & 15;
        dstv[(size_t)(base + node) * ROW4 + c] =
            reinterpret_cast<float4*>(&sAgg[node * AGG_STRIDE])[c];
    }
}

// ---------------- gather + loss ----------------

__global__ void gather_kernel(const float* __restrict__ emb,
                              const int* __restrict__ user,
                              const int* __restrict__ pos,
                              const int* __restrict__ neg,
                              int layer) {
    unsigned t = blockIdx.x * blockDim.x + threadIdx.x;
    if (t >= BB * 16) return;
    unsigned i = t >> 4;
    unsigned c = t & 15u;
    unsigned doff = i * 64 + (unsigned)layer * 16 + c;
    const float4* ev = reinterpret_cast<const float4*>(emb);
    reinterpret_cast<float4*>(g_ue)[doff] = ev[(size_t)user[i] * ROW4 + c];
    reinterpret_cast<float4*>(g_pe)[doff] = ev[(size_t)pos [i] * ROW4 + c];
    reinterpret_cast<float4*>(g_ne)[doff] = ev[(size_t)neg [i] * ROW4 + c];
}

__global__ void zero_out_kernel(float* out) {
    if (threadIdx.x == 0 && blockIdx.x == 0) out[0] = 0.f;
}

__global__ void loss_kernel(float* __restrict__ out) {
    int i = blockIdx.x * blockDim.x + threadIdx.x;
    float dp = 0.f, dn = 0.f;
    if (i < BB) {
        const float4* uv = reinterpret_cast<const float4*>(g_ue);
        const float4* pv = reinterpret_cast<const float4*>(g_pe);
        const float4* nv = reinterpret_cast<const float4*>(g_ne);
#pragma unroll 8
        for (int c = 0; c < 64; c++) {
            float4 u = uv[(size_t)i * 64 + c];
            float4 p = pv[(size_t)i * 64 + c];
            float4 q = nv[(size_t)i * 64 + c];
            dp += u.x*p.x + u.y*p.y + u.z*p.z + u.w*p.w;
            dn += u.x*q.x + u.y*q.y + u.z*q.z + u.w*q.w;
        }
    }
    float d = dp - dn;
    float l = (i < BB) ? (fmaxf(-d, 0.f) + log1pf(expf(-fabsf(d)))) : 0.f;

    __shared__ float red[256];
    red[threadIdx.x] = l;
    __syncthreads();
    for (int s = 128; s > 0; s >>= 1) {
        if (threadIdx.x < s) red[threadIdx.x] += red[threadIdx.x + s];
        __syncthreads();
    }
    if (threadIdx.x == 0) atomicAdd(out, red[0]);
}

// ---------------- launch ----------------

extern "C" void kernel_launch(void* const* d_in, const int* in_sizes, int n_in,
                              void* d_out, int out_size) {
    const float* emb  = (const float*)d_in[0];
    const float* w1w  = (const float*)d_in[1];
    const float* w1b  = (const float*)d_in[2];
    const float* w2w  = (const float*)d_in[3];
    const float* w2b  = (const float*)d_in[4];
    const float* vals = (const float*)d_in[5];
    const int*   rows = (const int*)d_in[6];
    const int*   cols = (const int*)d_in[7];
    const int*   user = (const int*)d_in[8];
    const int*   pos  = (const int*)d_in[9];
    const int*   neg  = (const int*)d_in[10];
    float* out = (float*)d_out;

    void *pA = nullptr, *pB = nullptr;
    cudaGetSymbolAddress(&pA, g_embA);
    cudaGetSymbolAddress(&pB, g_embB);
    float* eA = (float*)pA;
    float* eB = (float*)pB;

    const int SMEM_BYTES = SM_FLOATS * 4;   // 68096
    cudaFuncSetAttribute(dense_kernel,
                         cudaFuncAttributeMaxDynamicSharedMemorySize, SMEM_BYTES);

    const int EB = (EE + 255) / 256;          // edge-parallel grids
    const int NB = (NN + 255) / 256;
    const int SPB = (NN + 7) / 8;             // 8 warps/block, warp per row
    const int DB = (NN + 127) / 128;
    const int GB = (BB * 16 + 255) / 256;

    // ---- CSR build (per launch; deterministic workload) ----
    zero_cnt_kernel<<<NB, 256>>>();
    hist_kernel<<<EB, 256>>>(rows);
    scan_kernel<<<1, SCAN_T>>>();
    scatter_kernel<<<EB, 256>>>(rows, cols, vals);

    // layer 0 input gather
    gather_kernel<<<GB, 256>>>(emb, user, pos, neg, 0);

    // layer 1: emb -> eA
    spmm_csr_kernel<<<SPB, 256>>>(emb);
    dense_kernel<<<DB, 128, SMEM_BYTES>>>(emb, w1w, w1b, w2w, w2b, eA);
    gather_kernel<<<GB, 256>>>(eA, user, pos, neg, 1);

    // layer 2: eA -> eB
    spmm_csr_kernel<<<SPB, 256>>>(eA);
    dense_kernel<<<DB, 128, SMEM_BYTES>>>(eA, w1w + 4096, w1b + 64, w2w + 4096, w2b + 64, eB);
    gather_kernel<<<GB, 256>>>(eB, user, pos, neg, 2);

    // layer 3: eB -> eA
    spmm_csr_kernel<<<SPB, 256>>>(eB);
    dense_kernel<<<DB, 128, SMEM_BYTES>>>(eB, w1w + 8192, w1b + 128, w2w + 8192, w2b + 128, eA);
    gather_kernel<<<GB, 256>>>(eA, user, pos, neg, 3);

    // loss
    zero_out_kernel<<<1, 32>>>(out);
    loss_kernel<<<BB / 256, 256>>>(out);
}